// round 11
// baseline (speedup 1.0000x reference)
#include <cuda_runtime.h>
#include <cuda_fp16.h>
#include <cstdint>

// ---------------------------------------------------------------------------
// AttentionRAR: x -> qkv GEMM -> causal flash attention -> proj GEMM (+bias)
// B=4, N=2048, C=1024, H=16, D=64
// GEMMs: mma.sync fp16 with fp16 accumulators (spilled to fp32 every K=64)
// and 2-term one-sided split: a*b ~= (a_hi+a_lo)*b_hi.
// Attention: fp16 mma, fp32 acc (unchanged from R10).
// ---------------------------------------------------------------------------

#define BATCH 4
#define SEQ   2048
#define CH    1024
#define HEADS 16
#define HDIM  64
#define ROWS  (BATCH * SEQ)       // 8192
#define QKV_C (3 * CH)            // 3072
#define K2    (2 * CH)            // split K = 2048

// Scratch
__device__ __align__(1024) __half g_qh [(size_t)ROWS * QKV_C];  // qkv hi (fp16)
__device__ __align__(1024) __half g_qlo[(size_t)ROWS * CH];     // q lo   (fp16)
__device__ __align__(1024) __half g_xs [(size_t)ROWS * K2];
__device__ __align__(1024) __half g_as [(size_t)ROWS * K2];
__device__ __align__(1024) __half g_wqkt[(size_t)QKV_C * K2];
__device__ __align__(1024) __half g_wpt [(size_t)CH * K2];

// ======================= helpers ===========================================
__device__ __forceinline__ uint32_t smem_u32(const void* p) {
    uint32_t a;
    asm("{ .reg .u64 t; cvta.to.shared.u64 t, %1; cvt.u32.u64 %0, t; }"
        : "=r"(a) : "l"(p));
    return a;
}

#define CP_ASYNC16(sm, gp) \
    asm volatile("cp.async.cg.shared.global [%0], [%1], 16;" :: "r"(sm), "l"(gp))
#define CP_COMMIT() asm volatile("cp.async.commit_group;" ::: "memory")
#define CP_WAIT1()  asm volatile("cp.async.wait_group 1;" ::: "memory")

__device__ __forceinline__ void ldsm_x4(uint32_t& r0, uint32_t& r1,
                                        uint32_t& r2, uint32_t& r3, uint32_t a) {
    asm volatile("ldmatrix.sync.aligned.m8n8.x4.shared.b16 {%0,%1,%2,%3}, [%4];"
                 : "=r"(r0), "=r"(r1), "=r"(r2), "=r"(r3) : "r"(a));
}
__device__ __forceinline__ void ldsm_x4t(uint32_t& r0, uint32_t& r1,
                                         uint32_t& r2, uint32_t& r3, uint32_t a) {
    asm volatile("ldmatrix.sync.aligned.m8n8.x4.trans.shared.b16 {%0,%1,%2,%3}, [%4];"
                 : "=r"(r0), "=r"(r1), "=r"(r2), "=r"(r3) : "r"(a));
}
// fp32-acc mma (attention)
__device__ __forceinline__ void mma16816(float* c, const uint32_t* a,
                                         const uint32_t* b) {
    asm volatile("mma.sync.aligned.m16n8k16.row.col.f32.f16.f16.f32 "
                 "{%0,%1,%2,%3}, {%4,%5,%6,%7}, {%8,%9}, {%0,%1,%2,%3};"
                 : "+f"(c[0]), "+f"(c[1]), "+f"(c[2]), "+f"(c[3])
                 : "r"(a[0]), "r"(a[1]), "r"(a[2]), "r"(a[3]),
                   "r"(b[0]), "r"(b[1]));
}
// fp16-acc mma (GEMM inner)
__device__ __forceinline__ void mma16816h(uint32_t* c, const uint32_t* a,
                                          const uint32_t* b) {
    asm volatile("mma.sync.aligned.m16n8k16.row.col.f16.f16.f16.f16 "
                 "{%0,%1}, {%2,%3,%4,%5}, {%6,%7}, {%0,%1};"
                 : "+r"(c[0]), "+r"(c[1])
                 : "r"(a[0]), "r"(a[1]), "r"(a[2]), "r"(a[3]),
                   "r"(b[0]), "r"(b[1]));
}
__device__ __forceinline__ uint32_t pack_h2(float a, float b) {
    __half2 h = __floats2half2_rn(a, b);
    return *(uint32_t*)&h;
}

// ---------------------------------------------------------------------------
// Split conversions
// ---------------------------------------------------------------------------
__global__ void split_rows(const float* __restrict__ in, __half* __restrict__ out)
{
    size_t i = (size_t)blockIdx.x * blockDim.x + threadIdx.x;   // over ROWS*CH
    int r = (int)(i >> 10);
    int k = (int)(i & 1023);
    float a = in[i];
    __half hi = __float2half(a);
    __half lo = __float2half(a - __half2float(hi));
    __half* o = out + (size_t)r * K2;
    o[k] = hi; o[CH + k] = lo;
}

__global__ void split_wT(const float* __restrict__ W, __half* __restrict__ Wt, int N)
{
    __shared__ float t[32][33];
    int n0 = blockIdx.x * 32, k0 = blockIdx.y * 32;
    int tx = threadIdx.x, ty = threadIdx.y;   // 32 x 8
    #pragma unroll
    for (int j = 0; j < 32; j += 8)
        t[ty + j][tx] = W[(size_t)(k0 + ty + j) * N + n0 + tx];
    __syncthreads();
    #pragma unroll
    for (int j = 0; j < 32; j += 8) {
        float a = t[tx][ty + j];
        __half hi = __float2half(a);
        __half* o = Wt + (size_t)(n0 + ty + j) * K2 + k0 + tx;
        o[0] = hi; o[CH] = hi;
    }
}

// ---------------------------------------------------------------------------
// mma.sync fp16 GEMM, fp16 accumulators spilled to fp32 every 2 chunks (K=64).
// 128x128 CTA tile, BK=32, 8 warps (2x4), warp tile 64x32, 3-stage ring.
// MODE 0: fp32 out + bias. MODE 1: fp16 hi out (+ lo for cols < CH).
// ---------------------------------------------------------------------------
#define BK   32
#define LDSW 40
#define NCHUNK (K2 / BK)            // 64
#define ASTG (128 * LDSW * 2)       // 10240 B per stage per operand
#define NSTG 3
#define GSM_BYTES (2 * NSTG * ASTG) // 61440

template<int MODE>
__global__ __launch_bounds__(256)
void gemm_mma(const __half* __restrict__ A, const __half* __restrict__ Bt,
              const float* __restrict__ bias, float* __restrict__ C,
              __half* __restrict__ Ch, __half* __restrict__ Clo, int N)
{
    extern __shared__ __align__(128) char gsm[];
    const uint32_t sb = smem_u32(gsm);

    const int tid  = threadIdx.x;
    const int lane = tid & 31;
    const int warp = tid >> 5;
    const int wm   = warp >> 2;      // 0..1
    const int wn   = warp & 3;       // 0..3
    const int m0   = blockIdx.y * 128;
    const int n0   = blockIdx.x * 128;

    const int crow = tid >> 2;
    const int ckp  = (tid & 3) * 8;
    const uint32_t so0 = (uint32_t)(crow * LDSW + ckp) * 2;
    const uint32_t so1 = (uint32_t)((crow + 64) * LDSW + ckp) * 2;

    auto load = [&](int kc, int buf) {
        const uint32_t sA = sb + buf * ASTG;
        const uint32_t sB = sb + NSTG * ASTG + buf * ASTG;
        const __half* Ag = A + (size_t)(m0 + crow) * K2 + kc * BK + ckp;
        const __half* Bg = Bt + (size_t)(n0 + crow) * K2 + kc * BK + ckp;
        CP_ASYNC16(sA + so0, Ag);
        CP_ASYNC16(sA + so1, Ag + (size_t)64 * K2);
        CP_ASYNC16(sB + so0, Bg);
        CP_ASYNC16(sB + so1, Bg + (size_t)64 * K2);
    };

    const int lmat = lane >> 3;
    const int lrow = lane & 7;
    const int a_row_base = wm * 64 + ((lmat & 1) << 3) + lrow;
    const int a_k_off    = (lmat >> 1) << 3;
    const int b_row_base = wn * 32 + ((lmat >> 1) << 3) + lrow;
    const int b_k_off    = (lmat & 1) << 3;

    float acc[4][4][4];
    #pragma unroll
    for (int i = 0; i < 4; i++)
        #pragma unroll
        for (int j = 0; j < 4; j++)
            #pragma unroll
            for (int q = 0; q < 4; q++) acc[i][j][q] = 0.0f;

    uint32_t hacc[4][4][2];
    #pragma unroll
    for (int i = 0; i < 4; i++)
        #pragma unroll
        for (int j = 0; j < 4; j++) { hacc[i][j][0] = 0u; hacc[i][j][1] = 0u; }

    load(0, 0); CP_COMMIT();
    load(1, 1); CP_COMMIT();

    for (int t = 0; t < NCHUNK; t++) {
        const int buf = t % NSTG;
        CP_WAIT1();
        __syncthreads();
        if (t + 2 < NCHUNK) load(t + 2, (t + 2) % NSTG);
        CP_COMMIT();

        const uint32_t sA = sb + buf * ASTG;
        const uint32_t sB = sb + NSTG * ASTG + buf * ASTG;
        #pragma unroll
        for (int ks = 0; ks < 2; ks++) {
            uint32_t a[4][4];
            #pragma unroll
            for (int mt = 0; mt < 4; mt++)
                ldsm_x4(a[mt][0], a[mt][1], a[mt][2], a[mt][3],
                        sA + (uint32_t)((a_row_base + mt * 16) * LDSW
                                        + ks * 16 + a_k_off) * 2);
            uint32_t b[2][4];
            #pragma unroll
            for (int jj = 0; jj < 2; jj++)
                ldsm_x4(b[jj][0], b[jj][1], b[jj][2], b[jj][3],
                        sB + (uint32_t)((b_row_base + jj * 16) * LDSW
                                        + ks * 16 + b_k_off) * 2);
            #pragma unroll
            for (int mt = 0; mt < 4; mt++)
                #pragma unroll
                for (int nf = 0; nf < 4; nf++)
                    mma16816h(hacc[mt][nf], a[mt], &b[nf >> 1][(nf & 1) * 2]);
        }

        if (t & 1) {   // spill fp16 partials to fp32 every 2 chunks (K=64)
            #pragma unroll
            for (int mt = 0; mt < 4; mt++)
                #pragma unroll
                for (int nf = 0; nf < 4; nf++) {
                    float2 f0 = __half22float2(*(__half2*)&hacc[mt][nf][0]);
                    float2 f1 = __half22float2(*(__half2*)&hacc[mt][nf][1]);
                    acc[mt][nf][0] += f0.x;  acc[mt][nf][1] += f0.y;
                    acc[mt][nf][2] += f1.x;  acc[mt][nf][3] += f1.y;
                    hacc[mt][nf][0] = 0u;    hacc[mt][nf][1] = 0u;
                }
        }
    }

    const int emb = m0 + wm * 64 + (lane >> 2);
    const int enb = n0 + wn * 32 + (lane & 3) * 2;
    #pragma unroll
    for (int mt = 0; mt < 4; mt++) {
        #pragma unroll
        for (int nf = 0; nf < 4; nf++) {
            const int en = enb + nf * 8;
            const int em0 = emb + mt * 16;
            float v0 = acc[mt][nf][0], v1 = acc[mt][nf][1];
            float v2 = acc[mt][nf][2], v3 = acc[mt][nf][3];
            if (MODE == 0) {
                float b0 = bias[en], b1 = bias[en + 1];
                *(float2*)(C + (size_t)em0 * N + en)       = make_float2(v0 + b0, v1 + b1);
                *(float2*)(C + (size_t)(em0 + 8) * N + en) = make_float2(v2 + b0, v3 + b1);
            } else {
                uint32_t hiA = pack_h2(v0, v1);
                uint32_t hiB = pack_h2(v2, v3);
                *(uint32_t*)(Ch + (size_t)em0 * QKV_C + en)       = hiA;
                *(uint32_t*)(Ch + (size_t)(em0 + 8) * QKV_C + en) = hiB;
                if (en < CH) {   // Q third: also write lo residual
                    __half2 hA = *(__half2*)&hiA;
                    __half2 hB = *(__half2*)&hiB;
                    *(uint32_t*)(Clo + (size_t)em0 * CH + en) =
                        pack_h2(v0 - __low2float(hA), v1 - __high2float(hA));
                    *(uint32_t*)(Clo + (size_t)(em0 + 8) * CH + en) =
                        pack_h2(v2 - __low2float(hB), v3 - __high2float(hB));
                }
            }
        }
    }
}

// ---------------------------------------------------------------------------
// Tensorized causal flash attention (fp16 mma, fp32 acc, 2-term split).
// Inputs: qkv hi (fp16) + Q lo (fp16), via cp.async; 3-stage KV ring.
// Epilogue writes split-fp16 proj input (g_as).
// ---------------------------------------------------------------------------
#define LDQ 136
#define LDK 72
#define QS_HALVES (128 * LDQ)              // 17408
#define KVSTG_HALVES (2 * 64 * LDK)        // 9216 (K tile then V tile)
#define AT_BYTES ((QS_HALVES + 3 * KVSTG_HALVES) * 2)   // 90112

__global__ __launch_bounds__(256, 2)
void flash_attn_mma(const __half* __restrict__ qh, const __half* __restrict__ qlo,
                    __half* __restrict__ as)
{
    extern __shared__ __align__(128) __half hsm[];
    const uint32_t sQ = smem_u32(hsm);

    const int tid  = threadIdx.x;
    const int lane = tid & 31;
    const int warp = tid >> 5;
    const int bh = blockIdx.y;
    const int b  = bh >> 4;
    const int h  = bh & 15;
    const int m0 = blockIdx.x * 128;

    const __half* Qh = qh + (size_t)b * SEQ * QKV_C + h * HDIM;
    const __half* Ql = qlo + (size_t)b * SEQ * CH + h * HDIM;
    const __half* Kh = Qh + CH;
    const __half* Vh = Qh + 2 * CH;

    auto kv_stage = [&](int s) -> uint32_t {
        return sQ + (uint32_t)(QS_HALVES + s * KVSTG_HALVES) * 2;
    };
    auto load_kv = [&](int t, int s) {
        const uint32_t sK = kv_stage(s);
        const uint32_t sV = sK + (uint32_t)(64 * LDK) * 2;
        #pragma unroll
        for (int i = 0; i < 2; i++) {
            int c = tid + i * 256;
            int r = c >> 3, j = (c & 7) * 8;
            size_t g = (size_t)(t * 64 + r) * QKV_C + j;
            CP_ASYNC16(sK + (uint32_t)(r * LDK + j) * 2, Kh + g);
            CP_ASYNC16(sV + (uint32_t)(r * LDK + j) * 2, Vh + g);
        }
    };

    #pragma unroll
    for (int i = 0; i < 4; i++) {
        int c = tid + i * 256;
        int r = c >> 3, j = (c & 7) * 8;
        CP_ASYNC16(sQ + (uint32_t)(r * LDQ + j) * 2,
                   Qh + (size_t)(m0 + r) * QKV_C + j);
        CP_ASYNC16(sQ + (uint32_t)(r * LDQ + 64 + j) * 2,
                   Ql + (size_t)(m0 + r) * CH + j);
    }
    load_kv(0, 0); CP_COMMIT();
    load_kv(1, 1); CP_COMMIT();

    const int lmat = lane >> 3;
    const int lrow = lane & 7;
    const int a_row = warp * 16 + ((lmat & 1) << 3) + lrow;
    const int a_k   = (lmat >> 1) << 3;
    const int bs_rb = ((lmat >> 1) << 3) + lrow;
    const int bs_k  = (lmat & 1) << 3;
    const int bv_r  = ((lmat & 1) << 3) + lrow;
    const int bv_c  = (lmat >> 1) << 3;

    float m_i[2] = {-1e30f, -1e30f};
    float l_i[2] = {0.0f, 0.0f};
    float oacc[8][4];
    #pragma unroll
    for (int nf = 0; nf < 8; nf++)
        #pragma unroll
        for (int q = 0; q < 4; q++) oacc[nf][q] = 0.0f;

    const int r0 = m0 + warp * 16 + (lane >> 2);
    const int r1 = r0 + 8;

    const int ntiles = (m0 >> 6) + 2;
    for (int t = 0; t < ntiles; t++) {
        const int k0 = t << 6;
        CP_WAIT1();
        __syncthreads();
        if (t + 2 < ntiles) load_kv(t + 2, (t + 2) % 3);
        CP_COMMIT();

        const uint32_t sK = kv_stage(t % 3);
        const uint32_t sV = sK + (uint32_t)(64 * LDK) * 2;

        // ---- S = (Q_hi + Q_lo) K_hi^T : 8 k16 steps ----
        float sacc[8][4];
        #pragma unroll
        for (int nf = 0; nf < 8; nf++)
            #pragma unroll
            for (int q = 0; q < 4; q++) sacc[nf][q] = 0.0f;

        #pragma unroll
        for (int s = 0; s < 8; s++) {
            const int qb = (s < 4) ? (s & 3) * 16 : 64 + (s & 3) * 16;
            const int kb = (s & 3) * 16;
            uint32_t a[4];
            ldsm_x4(a[0], a[1], a[2], a[3],
                    sQ + (uint32_t)(a_row * LDQ + qb + a_k) * 2);
            #pragma unroll
            for (int nt = 0; nt < 4; nt++) {
                uint32_t bb[4];
                ldsm_x4(bb[0], bb[1], bb[2], bb[3],
                        sK + (uint32_t)((nt * 16 + bs_rb) * LDK + kb + bs_k) * 2);
                mma16816(sacc[nt * 2],     a, &bb[0]);
                mma16816(sacc[nt * 2 + 1], a, &bb[2]);
            }
        }

        // ---- online softmax ----
        const bool need_mask = (k0 + 63 > m0 + warp * 16);
        float mx0 = -1e30f, mx1 = -1e30f;
        #pragma unroll
        for (int nf = 0; nf < 8; nf++) {
            const int cb = k0 + nf * 8 + ((lane & 3) << 1);
            float v0 = sacc[nf][0] * 0.125f;
            float v1 = sacc[nf][1] * 0.125f;
            float v2 = sacc[nf][2] * 0.125f;
            float v3 = sacc[nf][3] * 0.125f;
            if (need_mask) {
                if (cb     > r0) v0 = -1e30f;
                if (cb + 1 > r0) v1 = -1e30f;
                if (cb     > r1) v2 = -1e30f;
                if (cb + 1 > r1) v3 = -1e30f;
            }
            sacc[nf][0] = v0; sacc[nf][1] = v1;
            sacc[nf][2] = v2; sacc[nf][3] = v3;
            mx0 = fmaxf(mx0, fmaxf(v0, v1));
            mx1 = fmaxf(mx1, fmaxf(v2, v3));
        }
        mx0 = fmaxf(mx0, __shfl_xor_sync(0xffffffffu, mx0, 1));
        mx0 = fmaxf(mx0, __shfl_xor_sync(0xffffffffu, mx0, 2));
        mx1 = fmaxf(mx1, __shfl_xor_sync(0xffffffffu, mx1, 1));
        mx1 = fmaxf(mx1, __shfl_xor_sync(0xffffffffu, mx1, 2));

        const float mn0 = fmaxf(m_i[0], mx0);
        const float mn1 = fmaxf(m_i[1], mx1);
        const float cr0 = __expf(m_i[0] - mn0);
        const float cr1 = __expf(m_i[1] - mn1);
        m_i[0] = mn0; m_i[1] = mn1;

        float sm0 = 0.f, sm1 = 0.f;
        #pragma unroll
        for (int nf = 0; nf < 8; nf++) {
            float p0 = __expf(sacc[nf][0] - mn0);
            float p1 = __expf(sacc[nf][1] - mn0);
            float p2 = __expf(sacc[nf][2] - mn1);
            float p3 = __expf(sacc[nf][3] - mn1);
            sacc[nf][0] = p0; sacc[nf][1] = p1;
            sacc[nf][2] = p2; sacc[nf][3] = p3;
            sm0 += p0 + p1;  sm1 += p2 + p3;
        }
        sm0 += __shfl_xor_sync(0xffffffffu, sm0, 1);
        sm0 += __shfl_xor_sync(0xffffffffu, sm0, 2);
        sm1 += __shfl_xor_sync(0xffffffffu, sm1, 1);
        sm1 += __shfl_xor_sync(0xffffffffu, sm1, 2);
        l_i[0] = l_i[0] * cr0 + sm0;
        l_i[1] = l_i[1] * cr1 + sm1;
        #pragma unroll
        for (int nf = 0; nf < 8; nf++) {
            oacc[nf][0] *= cr0; oacc[nf][1] *= cr0;
            oacc[nf][2] *= cr1; oacc[nf][3] *= cr1;
        }

        // ---- O += (P_hi + P_lo) V_hi : 8 k16 steps ----
        #pragma unroll
        for (int s = 0; s < 8; s++) {
            const int ks = s & 3;
            const int kb = ks * 16;
            uint32_t pa[4];
            if (s < 4) {
                pa[0] = pack_h2(sacc[2 * ks][0],     sacc[2 * ks][1]);
                pa[1] = pack_h2(sacc[2 * ks][2],     sacc[2 * ks][3]);
                pa[2] = pack_h2(sacc[2 * ks + 1][0], sacc[2 * ks + 1][1]);
                pa[3] = pack_h2(sacc[2 * ks + 1][2], sacc[2 * ks + 1][3]);
            } else {
                #pragma unroll
                for (int hf = 0; hf < 2; hf++) {
                    const int nf = 2 * ks + hf;
                    uint32_t h01 = pack_h2(sacc[nf][0], sacc[nf][1]);
                    uint32_t h23 = pack_h2(sacc[nf][2], sacc[nf][3]);
                    __half2 b01 = *(__half2*)&h01;
                    __half2 b23 = *(__half2*)&h23;
                    pa[hf * 2]     = pack_h2(sacc[nf][0] - __low2float(b01),
                                             sacc[nf][1] - __high2float(b01));
                    pa[hf * 2 + 1] = pack_h2(sacc[nf][2] - __low2float(b23),
                                             sacc[nf][3] - __high2float(b23));
                }
            }
            #pragma unroll
            for (int nt = 0; nt < 4; nt++) {
                uint32_t bb[4];
                ldsm_x4t(bb[0], bb[1], bb[2], bb[3],
                         sV + (uint32_t)((kb + bv_r) * LDK + nt * 16 + bv_c) * 2);
                mma16816(oacc[nt * 2],     pa, &bb[0]);
                mma16816(oacc[nt * 2 + 1], pa, &bb[2]);
            }
        }
    }

    // ---- epilogue: normalize + fused split write to g_as [hi | lo] ----
    const float inv0 = 1.0f / l_i[0];
    const float inv1 = 1.0f / l_i[1];
    const size_t row0 = (size_t)(b * SEQ + r0) * K2;
    const size_t row1 = (size_t)(b * SEQ + r1) * K2;
    #pragma unroll
    for (int nf = 0; nf < 8; nf++) {
        const int col = h * HDIM + nf * 8 + ((lane & 3) << 1);
        float v0 = oacc[nf][0] * inv0, v1 = oacc[nf][1] * inv0;
        float v2 = oacc[nf][2] * inv1, v3 = oacc[nf][3] * inv1;

        uint32_t hiA = pack_h2(v0, v1);
        __half2 hA = *(__half2*)&hiA;
        uint32_t loA = pack_h2(v0 - __low2float(hA), v1 - __high2float(hA));
        uint32_t hiB = pack_h2(v2, v3);
        __half2 hB = *(__half2*)&hiB;
        uint32_t loB = pack_h2(v2 - __low2float(hB), v3 - __high2float(hB));

        *(uint32_t*)(as + row0 + col)      = hiA;
        *(uint32_t*)(as + row0 + CH + col) = loA;
        *(uint32_t*)(as + row1 + col)      = hiB;
        *(uint32_t*)(as + row1 + CH + col) = loB;
    }
}

// ---------------------------------------------------------------------------
extern "C" void kernel_launch(void* const* d_in, const int* in_sizes, int n_in,
                              void* d_out, int out_size)
{
    const float* x     = (const float*)d_in[0];
    const float* Wqkv  = (const float*)d_in[2];
    const float* Wproj = (const float*)d_in[3];
    const float* bproj = (const float*)d_in[4];
    float* out = (float*)d_out;

    void *p_qh, *p_qlo, *p_xs, *p_as, *p_wqkt, *p_wpt;
    cudaGetSymbolAddress(&p_qh, g_qh);
    cudaGetSymbolAddress(&p_qlo, g_qlo);
    cudaGetSymbolAddress(&p_xs, g_xs);
    cudaGetSymbolAddress(&p_as, g_as);
    cudaGetSymbolAddress(&p_wqkt, g_wqkt);
    cudaGetSymbolAddress(&p_wpt, g_wpt);
    __half* qh   = (__half*)p_qh;
    __half* qlo  = (__half*)p_qlo;
    __half* xs   = (__half*)p_xs;
    __half* as   = (__half*)p_as;
    __half* wqkt = (__half*)p_wqkt;
    __half* wpt  = (__half*)p_wpt;

    cudaFuncSetAttribute(gemm_mma<0>, cudaFuncAttributeMaxDynamicSharedMemorySize,
                         GSM_BYTES);
    cudaFuncSetAttribute(gemm_mma<1>, cudaFuncAttributeMaxDynamicSharedMemorySize,
                         GSM_BYTES);
    cudaFuncSetAttribute(flash_attn_mma, cudaFuncAttributeMaxDynamicSharedMemorySize,
                         AT_BYTES);

    // conversions
    split_rows<<<(ROWS * CH) / 256, 256>>>(x, xs);
    dim3 wt1(QKV_C / 32, CH / 32);
    split_wT<<<wt1, dim3(32, 8)>>>(Wqkv, wqkt, QKV_C);
    dim3 wt2(CH / 32, CH / 32);
    split_wT<<<wt2, dim3(32, 8)>>>(Wproj, wpt, CH);

    // 1) qkv = x @ W_qkv  -> fp16 hi (+ Q lo) directly
    dim3 g1(QKV_C / 128, ROWS / 128);
    gemm_mma<1><<<g1, 256, GSM_BYTES>>>(xs, wqkt, nullptr, nullptr, qh, qlo, QKV_C);

    // 2) causal flash attention -> split proj input (fused)
    dim3 g2(SEQ / 128, BATCH * HEADS);
    flash_attn_mma<<<g2, 256, AT_BYTES>>>(qh, qlo, as);

    // 3) out = attn @ W_proj + b
    dim3 g3(CH / 128, ROWS / 128);
    gemm_mma<0><<<g3, 256, GSM_BYTES>>>(as, wpt, bproj, out, nullptr, nullptr, CH);
}

// round 12
// speedup vs baseline: 1.3135x; 1.3135x over previous
#include <cuda_runtime.h>
#include <cuda_fp16.h>
#include <cstdint>

// ---------------------------------------------------------------------------
// AttentionRAR: x -> qkv GEMM -> causal flash attention -> proj GEMM (+bias)
// B=4, N=2048, C=1024, H=16, D=64
// mma.sync fp16, fp32 acc. Precision-split applied only where consumed:
//   Q cols:  split-K GEMM (x_hi + x_lo)            [K=2048]
//   K,V cols: hi-only GEMM (fp16 rounding dominates) [K=1024]
//   S = (Q_hi+Q_lo) K_hi^T ; O += P_hi V_hi ; proj: (a_hi+a_lo) W_hi
// ---------------------------------------------------------------------------

#define BATCH 4
#define SEQ   2048
#define CH    1024
#define HEADS 16
#define HDIM  64
#define ROWS  (BATCH * SEQ)       // 8192
#define QKV_C (3 * CH)            // 3072
#define K2    (2 * CH)            // split K = 2048

// Scratch
__device__ __align__(1024) __half g_qh [(size_t)ROWS * QKV_C];  // qkv hi (fp16)
__device__ __align__(1024) __half g_qlo[(size_t)ROWS * CH];     // q lo   (fp16)
__device__ __align__(1024) __half g_xs [(size_t)ROWS * K2];     // x  [hi | lo]
__device__ __align__(1024) __half g_as [(size_t)ROWS * K2];     // attn [hi | lo]
__device__ __align__(1024) __half g_wqkt[(size_t)QKV_C * K2];   // Wqkv^T [hi | hi]
__device__ __align__(1024) __half g_wpt [(size_t)CH * K2];      // Wproj^T [hi | hi]

// ======================= helpers ===========================================
__device__ __forceinline__ uint32_t smem_u32(const void* p) {
    uint32_t a;
    asm("{ .reg .u64 t; cvta.to.shared.u64 t, %1; cvt.u32.u64 %0, t; }"
        : "=r"(a) : "l"(p));
    return a;
}

#define CP_ASYNC16(sm, gp) \
    asm volatile("cp.async.cg.shared.global [%0], [%1], 16;" :: "r"(sm), "l"(gp))
#define CP_COMMIT() asm volatile("cp.async.commit_group;" ::: "memory")
#define CP_WAIT1()  asm volatile("cp.async.wait_group 1;" ::: "memory")

__device__ __forceinline__ void ldsm_x4(uint32_t& r0, uint32_t& r1,
                                        uint32_t& r2, uint32_t& r3, uint32_t a) {
    asm volatile("ldmatrix.sync.aligned.m8n8.x4.shared.b16 {%0,%1,%2,%3}, [%4];"
                 : "=r"(r0), "=r"(r1), "=r"(r2), "=r"(r3) : "r"(a));
}
__device__ __forceinline__ void ldsm_x4t(uint32_t& r0, uint32_t& r1,
                                         uint32_t& r2, uint32_t& r3, uint32_t a) {
    asm volatile("ldmatrix.sync.aligned.m8n8.x4.trans.shared.b16 {%0,%1,%2,%3}, [%4];"
                 : "=r"(r0), "=r"(r1), "=r"(r2), "=r"(r3) : "r"(a));
}
__device__ __forceinline__ void mma16816(float* c, const uint32_t* a,
                                         const uint32_t* b) {
    asm volatile("mma.sync.aligned.m16n8k16.row.col.f32.f16.f16.f32 "
                 "{%0,%1,%2,%3}, {%4,%5,%6,%7}, {%8,%9}, {%0,%1,%2,%3};"
                 : "+f"(c[0]), "+f"(c[1]), "+f"(c[2]), "+f"(c[3])
                 : "r"(a[0]), "r"(a[1]), "r"(a[2]), "r"(a[3]),
                   "r"(b[0]), "r"(b[1]));
}
__device__ __forceinline__ uint32_t pack_h2(float a, float b) {
    __half2 h = __floats2half2_rn(a, b);
    return *(uint32_t*)&h;
}

// ---------------------------------------------------------------------------
// Split conversions
// ---------------------------------------------------------------------------
__global__ void split_rows(const float* __restrict__ in, __half* __restrict__ out)
{
    size_t i = (size_t)blockIdx.x * blockDim.x + threadIdx.x;   // over ROWS*CH
    int r = (int)(i >> 10);
    int k = (int)(i & 1023);
    float a = in[i];
    __half hi = __float2half(a);
    __half lo = __float2half(a - __half2float(hi));
    __half* o = out + (size_t)r * K2;
    o[k] = hi; o[CH + k] = lo;
}

__global__ void split_wT(const float* __restrict__ W, __half* __restrict__ Wt, int N)
{
    __shared__ float t[32][33];
    int n0 = blockIdx.x * 32, k0 = blockIdx.y * 32;
    int tx = threadIdx.x, ty = threadIdx.y;   // 32 x 8
    #pragma unroll
    for (int j = 0; j < 32; j += 8)
        t[ty + j][tx] = W[(size_t)(k0 + ty + j) * N + n0 + tx];
    __syncthreads();
    #pragma unroll
    for (int j = 0; j < 32; j += 8) {
        float a = t[tx][ty + j];
        __half hi = __float2half(a);
        __half* o = Wt + (size_t)(n0 + ty + j) * K2 + k0 + tx;
        o[0] = hi; o[CH] = hi;
    }
}

// ---------------------------------------------------------------------------
// mma.sync fp16 GEMM, fp32 acc. 128x128 CTA tile, BK=32, 8 warps (2x4),
// warp tile 64x32, 3-stage cp.async ring. Runtime chunk count.
// MODE 0: fp32 out + bias.  MODE 1: Q cols -> hi + lo.  MODE 2: KV cols -> hi.
// ---------------------------------------------------------------------------
#define BK   32
#define LDSW 40
#define ASTG (128 * LDSW * 2)       // 10240 B per stage per operand
#define NSTG 3
#define GSM_BYTES (2 * NSTG * ASTG) // 61440

template<int MODE>
__global__ __launch_bounds__(256)
void gemm_mma(const __half* __restrict__ A, const __half* __restrict__ Bt,
              const float* __restrict__ bias, float* __restrict__ C,
              __half* __restrict__ Ch, __half* __restrict__ Clo,
              int N, int nchunk)
{
    extern __shared__ __align__(128) char gsm[];
    const uint32_t sb = smem_u32(gsm);

    const int tid  = threadIdx.x;
    const int lane = tid & 31;
    const int warp = tid >> 5;
    const int wm   = warp >> 2;      // 0..1
    const int wn   = warp & 3;       // 0..3
    const int m0   = blockIdx.y * 128;
    const int n0   = blockIdx.x * 128;

    const int crow = tid >> 2;
    const int ckp  = (tid & 3) * 8;
    const uint32_t so0 = (uint32_t)(crow * LDSW + ckp) * 2;
    const uint32_t so1 = (uint32_t)((crow + 64) * LDSW + ckp) * 2;

    auto load = [&](int kc, int buf) {
        const uint32_t sA = sb + buf * ASTG;
        const uint32_t sB = sb + NSTG * ASTG + buf * ASTG;
        const __half* Ag = A + (size_t)(m0 + crow) * K2 + kc * BK + ckp;
        const __half* Bg = Bt + (size_t)(n0 + crow) * K2 + kc * BK + ckp;
        CP_ASYNC16(sA + so0, Ag);
        CP_ASYNC16(sA + so1, Ag + (size_t)64 * K2);
        CP_ASYNC16(sB + so0, Bg);
        CP_ASYNC16(sB + so1, Bg + (size_t)64 * K2);
    };

    const int lmat = lane >> 3;
    const int lrow = lane & 7;
    const int a_row_base = wm * 64 + ((lmat & 1) << 3) + lrow;
    const int a_k_off    = (lmat >> 1) << 3;
    const int b_row_base = wn * 32 + ((lmat >> 1) << 3) + lrow;
    const int b_k_off    = (lmat & 1) << 3;

    float acc[4][4][4];
    #pragma unroll
    for (int i = 0; i < 4; i++)
        #pragma unroll
        for (int j = 0; j < 4; j++)
            #pragma unroll
            for (int q = 0; q < 4; q++) acc[i][j][q] = 0.0f;

    load(0, 0); CP_COMMIT();
    load(1, 1); CP_COMMIT();

    for (int t = 0; t < nchunk; t++) {
        const int buf = t % NSTG;
        CP_WAIT1();
        __syncthreads();
        if (t + 2 < nchunk) load(t + 2, (t + 2) % NSTG);
        CP_COMMIT();

        const uint32_t sA = sb + buf * ASTG;
        const uint32_t sB = sb + NSTG * ASTG + buf * ASTG;
        #pragma unroll
        for (int ks = 0; ks < 2; ks++) {
            uint32_t a[4][4];
            #pragma unroll
            for (int mt = 0; mt < 4; mt++)
                ldsm_x4(a[mt][0], a[mt][1], a[mt][2], a[mt][3],
                        sA + (uint32_t)((a_row_base + mt * 16) * LDSW
                                        + ks * 16 + a_k_off) * 2);
            uint32_t b[2][4];
            #pragma unroll
            for (int jj = 0; jj < 2; jj++)
                ldsm_x4(b[jj][0], b[jj][1], b[jj][2], b[jj][3],
                        sB + (uint32_t)((b_row_base + jj * 16) * LDSW
                                        + ks * 16 + b_k_off) * 2);
            #pragma unroll
            for (int mt = 0; mt < 4; mt++)
                #pragma unroll
                for (int nf = 0; nf < 4; nf++)
                    mma16816(acc[mt][nf], a[mt], &b[nf >> 1][(nf & 1) * 2]);
        }
    }

    const int emb = m0 + wm * 64 + (lane >> 2);
    const int enb = n0 + wn * 32 + (lane & 3) * 2;
    #pragma unroll
    for (int mt = 0; mt < 4; mt++) {
        #pragma unroll
        for (int nf = 0; nf < 4; nf++) {
            const int en = enb + nf * 8;
            const int em0 = emb + mt * 16;
            float v0 = acc[mt][nf][0], v1 = acc[mt][nf][1];
            float v2 = acc[mt][nf][2], v3 = acc[mt][nf][3];
            if (MODE == 0) {
                float b0 = bias[en], b1 = bias[en + 1];
                *(float2*)(C + (size_t)em0 * N + en)       = make_float2(v0 + b0, v1 + b1);
                *(float2*)(C + (size_t)(em0 + 8) * N + en) = make_float2(v2 + b0, v3 + b1);
            } else if (MODE == 1) {          // Q columns: hi + lo
                uint32_t hiA = pack_h2(v0, v1);
                uint32_t hiB = pack_h2(v2, v3);
                *(uint32_t*)(Ch + (size_t)em0 * QKV_C + en)       = hiA;
                *(uint32_t*)(Ch + (size_t)(em0 + 8) * QKV_C + en) = hiB;
                __half2 hA = *(__half2*)&hiA;
                __half2 hB = *(__half2*)&hiB;
                *(uint32_t*)(Clo + (size_t)em0 * CH + en) =
                    pack_h2(v0 - __low2float(hA), v1 - __high2float(hA));
                *(uint32_t*)(Clo + (size_t)(em0 + 8) * CH + en) =
                    pack_h2(v2 - __low2float(hB), v3 - __high2float(hB));
            } else {                          // KV columns: hi only, offset CH
                *(uint32_t*)(Ch + (size_t)em0 * QKV_C + CH + en)       = pack_h2(v0, v1);
                *(uint32_t*)(Ch + (size_t)(em0 + 8) * QKV_C + CH + en) = pack_h2(v2, v3);
            }
        }
    }
}

// ---------------------------------------------------------------------------
// Tensorized causal flash attention (fp16 mma, fp32 acc).
// S = (Q_hi+Q_lo) K_hi^T (8 steps); O += P_hi V_hi (4 steps).
// 3-stage KV cp.async ring. Epilogue writes split proj input (g_as).
// ---------------------------------------------------------------------------
#define LDQ 136
#define LDK 72
#define QS_HALVES (128 * LDQ)              // 17408
#define KVSTG_HALVES (2 * 64 * LDK)        // 9216
#define AT_BYTES ((QS_HALVES + 3 * KVSTG_HALVES) * 2)   // 90112

__global__ __launch_bounds__(256, 2)
void flash_attn_mma(const __half* __restrict__ qh, const __half* __restrict__ qlo,
                    __half* __restrict__ as)
{
    extern __shared__ __align__(128) __half hsm[];
    const uint32_t sQ = smem_u32(hsm);

    const int tid  = threadIdx.x;
    const int lane = tid & 31;
    const int warp = tid >> 5;
    const int bh = blockIdx.y;
    const int b  = bh >> 4;
    const int h  = bh & 15;
    const int m0 = blockIdx.x * 128;

    const __half* Qh = qh + (size_t)b * SEQ * QKV_C + h * HDIM;
    const __half* Ql = qlo + (size_t)b * SEQ * CH + h * HDIM;
    const __half* Kh = Qh + CH;
    const __half* Vh = Qh + 2 * CH;

    auto kv_stage = [&](int s) -> uint32_t {
        return sQ + (uint32_t)(QS_HALVES + s * KVSTG_HALVES) * 2;
    };
    auto load_kv = [&](int t, int s) {
        const uint32_t sK = kv_stage(s);
        const uint32_t sV = sK + (uint32_t)(64 * LDK) * 2;
        #pragma unroll
        for (int i = 0; i < 2; i++) {
            int c = tid + i * 256;
            int r = c >> 3, j = (c & 7) * 8;
            size_t g = (size_t)(t * 64 + r) * QKV_C + j;
            CP_ASYNC16(sK + (uint32_t)(r * LDK + j) * 2, Kh + g);
            CP_ASYNC16(sV + (uint32_t)(r * LDK + j) * 2, Vh + g);
        }
    };

    #pragma unroll
    for (int i = 0; i < 4; i++) {
        int c = tid + i * 256;
        int r = c >> 3, j = (c & 7) * 8;
        CP_ASYNC16(sQ + (uint32_t)(r * LDQ + j) * 2,
                   Qh + (size_t)(m0 + r) * QKV_C + j);
        CP_ASYNC16(sQ + (uint32_t)(r * LDQ + 64 + j) * 2,
                   Ql + (size_t)(m0 + r) * CH + j);
    }
    load_kv(0, 0); CP_COMMIT();
    load_kv(1, 1); CP_COMMIT();

    const int lmat = lane >> 3;
    const int lrow = lane & 7;
    const int a_row = warp * 16 + ((lmat & 1) << 3) + lrow;
    const int a_k   = (lmat >> 1) << 3;
    const int bs_rb = ((lmat >> 1) << 3) + lrow;
    const int bs_k  = (lmat & 1) << 3;
    const int bv_r  = ((lmat & 1) << 3) + lrow;
    const int bv_c  = (lmat >> 1) << 3;

    float m_i[2] = {-1e30f, -1e30f};
    float l_i[2] = {0.0f, 0.0f};
    float oacc[8][4];
    #pragma unroll
    for (int nf = 0; nf < 8; nf++)
        #pragma unroll
        for (int q = 0; q < 4; q++) oacc[nf][q] = 0.0f;

    const int r0 = m0 + warp * 16 + (lane >> 2);
    const int r1 = r0 + 8;

    const int ntiles = (m0 >> 6) + 2;
    for (int t = 0; t < ntiles; t++) {
        const int k0 = t << 6;
        CP_WAIT1();
        __syncthreads();
        if (t + 2 < ntiles) load_kv(t + 2, (t + 2) % 3);
        CP_COMMIT();

        const uint32_t sK = kv_stage(t % 3);
        const uint32_t sV = sK + (uint32_t)(64 * LDK) * 2;

        // ---- S = (Q_hi + Q_lo) K_hi^T : 8 k16 steps ----
        float sacc[8][4];
        #pragma unroll
        for (int nf = 0; nf < 8; nf++)
            #pragma unroll
            for (int q = 0; q < 4; q++) sacc[nf][q] = 0.0f;

        #pragma unroll
        for (int s = 0; s < 8; s++) {
            const int qb = (s < 4) ? (s & 3) * 16 : 64 + (s & 3) * 16;
            const int kb = (s & 3) * 16;
            uint32_t a[4];
            ldsm_x4(a[0], a[1], a[2], a[3],
                    sQ + (uint32_t)(a_row * LDQ + qb + a_k) * 2);
            #pragma unroll
            for (int nt = 0; nt < 4; nt++) {
                uint32_t bb[4];
                ldsm_x4(bb[0], bb[1], bb[2], bb[3],
                        sK + (uint32_t)((nt * 16 + bs_rb) * LDK + kb + bs_k) * 2);
                mma16816(sacc[nt * 2],     a, &bb[0]);
                mma16816(sacc[nt * 2 + 1], a, &bb[2]);
            }
        }

        // ---- online softmax ----
        const bool need_mask = (k0 + 63 > m0 + warp * 16);
        float mx0 = -1e30f, mx1 = -1e30f;
        #pragma unroll
        for (int nf = 0; nf < 8; nf++) {
            const int cb = k0 + nf * 8 + ((lane & 3) << 1);
            float v0 = sacc[nf][0] * 0.125f;
            float v1 = sacc[nf][1] * 0.125f;
            float v2 = sacc[nf][2] * 0.125f;
            float v3 = sacc[nf][3] * 0.125f;
            if (need_mask) {
                if (cb     > r0) v0 = -1e30f;
                if (cb + 1 > r0) v1 = -1e30f;
                if (cb     > r1) v2 = -1e30f;
                if (cb + 1 > r1) v3 = -1e30f;
            }
            sacc[nf][0] = v0; sacc[nf][1] = v1;
            sacc[nf][2] = v2; sacc[nf][3] = v3;
            mx0 = fmaxf(mx0, fmaxf(v0, v1));
            mx1 = fmaxf(mx1, fmaxf(v2, v3));
        }
        mx0 = fmaxf(mx0, __shfl_xor_sync(0xffffffffu, mx0, 1));
        mx0 = fmaxf(mx0, __shfl_xor_sync(0xffffffffu, mx0, 2));
        mx1 = fmaxf(mx1, __shfl_xor_sync(0xffffffffu, mx1, 1));
        mx1 = fmaxf(mx1, __shfl_xor_sync(0xffffffffu, mx1, 2));

        const float mn0 = fmaxf(m_i[0], mx0);
        const float mn1 = fmaxf(m_i[1], mx1);
        const float cr0 = __expf(m_i[0] - mn0);
        const float cr1 = __expf(m_i[1] - mn1);
        m_i[0] = mn0; m_i[1] = mn1;

        float sm0 = 0.f, sm1 = 0.f;
        #pragma unroll
        for (int nf = 0; nf < 8; nf++) {
            float p0 = __expf(sacc[nf][0] - mn0);
            float p1 = __expf(sacc[nf][1] - mn0);
            float p2 = __expf(sacc[nf][2] - mn1);
            float p3 = __expf(sacc[nf][3] - mn1);
            sacc[nf][0] = p0; sacc[nf][1] = p1;
            sacc[nf][2] = p2; sacc[nf][3] = p3;
            sm0 += p0 + p1;  sm1 += p2 + p3;
        }
        sm0 += __shfl_xor_sync(0xffffffffu, sm0, 1);
        sm0 += __shfl_xor_sync(0xffffffffu, sm0, 2);
        sm1 += __shfl_xor_sync(0xffffffffu, sm1, 1);
        sm1 += __shfl_xor_sync(0xffffffffu, sm1, 2);
        l_i[0] = l_i[0] * cr0 + sm0;
        l_i[1] = l_i[1] * cr1 + sm1;
        #pragma unroll
        for (int nf = 0; nf < 8; nf++) {
            oacc[nf][0] *= cr0; oacc[nf][1] *= cr0;
            oacc[nf][2] *= cr1; oacc[nf][3] *= cr1;
        }

        // ---- O += P_hi V_hi : 4 k16 steps ----
        #pragma unroll
        for (int s = 0; s < 4; s++) {
            const int kb = s * 16;
            uint32_t pa[4];
            pa[0] = pack_h2(sacc[2 * s][0],     sacc[2 * s][1]);
            pa[1] = pack_h2(sacc[2 * s][2],     sacc[2 * s][3]);
            pa[2] = pack_h2(sacc[2 * s + 1][0], sacc[2 * s + 1][1]);
            pa[3] = pack_h2(sacc[2 * s + 1][2], sacc[2 * s + 1][3]);
            #pragma unroll
            for (int nt = 0; nt < 4; nt++) {
                uint32_t bb[4];
                ldsm_x4t(bb[0], bb[1], bb[2], bb[3],
                         sV + (uint32_t)((kb + bv_r) * LDK + nt * 16 + bv_c) * 2);
                mma16816(oacc[nt * 2],     pa, &bb[0]);
                mma16816(oacc[nt * 2 + 1], pa, &bb[2]);
            }
        }
    }

    // ---- epilogue: normalize + fused split write to g_as [hi | lo] ----
    const float inv0 = 1.0f / l_i[0];
    const float inv1 = 1.0f / l_i[1];
    const size_t row0 = (size_t)(b * SEQ + r0) * K2;
    const size_t row1 = (size_t)(b * SEQ + r1) * K2;
    #pragma unroll
    for (int nf = 0; nf < 8; nf++) {
        const int col = h * HDIM + nf * 8 + ((lane & 3) << 1);
        float v0 = oacc[nf][0] * inv0, v1 = oacc[nf][1] * inv0;
        float v2 = oacc[nf][2] * inv1, v3 = oacc[nf][3] * inv1;

        uint32_t hiA = pack_h2(v0, v1);
        __half2 hA = *(__half2*)&hiA;
        uint32_t loA = pack_h2(v0 - __low2float(hA), v1 - __high2float(hA));
        uint32_t hiB = pack_h2(v2, v3);
        __half2 hB = *(__half2*)&hiB;
        uint32_t loB = pack_h2(v2 - __low2float(hB), v3 - __high2float(hB));

        *(uint32_t*)(as + row0 + col)      = hiA;
        *(uint32_t*)(as + row0 + CH + col) = loA;
        *(uint32_t*)(as + row1 + col)      = hiB;
        *(uint32_t*)(as + row1 + CH + col) = loB;
    }
}

// ---------------------------------------------------------------------------
extern "C" void kernel_launch(void* const* d_in, const int* in_sizes, int n_in,
                              void* d_out, int out_size)
{
    const float* x     = (const float*)d_in[0];
    const float* Wqkv  = (const float*)d_in[2];
    const float* Wproj = (const float*)d_in[3];
    const float* bproj = (const float*)d_in[4];
    float* out = (float*)d_out;

    void *p_qh, *p_qlo, *p_xs, *p_as, *p_wqkt, *p_wpt;
    cudaGetSymbolAddress(&p_qh, g_qh);
    cudaGetSymbolAddress(&p_qlo, g_qlo);
    cudaGetSymbolAddress(&p_xs, g_xs);
    cudaGetSymbolAddress(&p_as, g_as);
    cudaGetSymbolAddress(&p_wqkt, g_wqkt);
    cudaGetSymbolAddress(&p_wpt, g_wpt);
    __half* qh   = (__half*)p_qh;
    __half* qlo  = (__half*)p_qlo;
    __half* xs   = (__half*)p_xs;
    __half* as   = (__half*)p_as;
    __half* wqkt = (__half*)p_wqkt;
    __half* wpt  = (__half*)p_wpt;

    cudaFuncSetAttribute(gemm_mma<0>, cudaFuncAttributeMaxDynamicSharedMemorySize,
                         GSM_BYTES);
    cudaFuncSetAttribute(gemm_mma<1>, cudaFuncAttributeMaxDynamicSharedMemorySize,
                         GSM_BYTES);
    cudaFuncSetAttribute(gemm_mma<2>, cudaFuncAttributeMaxDynamicSharedMemorySize,
                         GSM_BYTES);
    cudaFuncSetAttribute(flash_attn_mma, cudaFuncAttributeMaxDynamicSharedMemorySize,
                         AT_BYTES);

    // conversions
    split_rows<<<(ROWS * CH) / 256, 256>>>(x, xs);
    dim3 wt1(QKV_C / 32, CH / 32);
    split_wT<<<wt1, dim3(32, 8)>>>(Wqkv, wqkt, QKV_C);
    dim3 wt2(CH / 32, CH / 32);
    split_wT<<<wt2, dim3(32, 8)>>>(Wproj, wpt, CH);

    // 1a) Q cols: split-K GEMM (K=2048) -> hi + lo
    dim3 gq(CH / 128, ROWS / 128);
    gemm_mma<1><<<gq, 256, GSM_BYTES>>>(xs, wqkt, nullptr, nullptr, qh, qlo,
                                        CH, K2 / BK);
    // 1b) K,V cols: hi-only GEMM (K=1024) -> hi
    dim3 gkv((2 * CH) / 128, ROWS / 128);
    gemm_mma<2><<<gkv, 256, GSM_BYTES>>>(xs, wqkt + (size_t)CH * K2, nullptr,
                                         nullptr, qh, nullptr, 2 * CH, CH / BK);

    // 2) causal flash attention -> split proj input (fused)
    dim3 g2(SEQ / 128, BATCH * HEADS);
    flash_attn_mma<<<g2, 256, AT_BYTES>>>(qh, qlo, as);

    // 3) out = attn @ W_proj + b
    dim3 g3(CH / 128, ROWS / 128);
    gemm_mma<0><<<g3, 256, GSM_BYTES>>>(as, wpt, bproj, out, nullptr, nullptr,
                                        CH, K2 / BK);
}

// round 13
// speedup vs baseline: 1.5598x; 1.1875x over previous
#include <cuda_runtime.h>
#include <cuda_fp16.h>
#include <cstdint>

// ---------------------------------------------------------------------------
// AttentionRAR: x -> qkv GEMM -> causal flash attention -> proj GEMM (+bias)
// B=4, N=2048, C=1024, H=16, D=64
// mma.sync fp16, fp32 acc.
//   qkv:  hi-only fp16 GEMM (K=1024, single launch, N=3072)
//   attn: S = Q_hi K_hi^T (4 steps); O += P_hi V_hi (4 steps)
//   proj: 2-term split (a_hi + a_lo) @ W_hi   [K=2048]  <- precision anchor
// ---------------------------------------------------------------------------

#define BATCH 4
#define SEQ   2048
#define CH    1024
#define HEADS 16
#define HDIM  64
#define ROWS  (BATCH * SEQ)       // 8192
#define QKV_C (3 * CH)            // 3072
#define K2    (2 * CH)            // split K = 2048

// Scratch
__device__ __align__(1024) __half g_qh [(size_t)ROWS * QKV_C];  // qkv hi (fp16)
__device__ __align__(1024) __half g_xh [(size_t)ROWS * CH];     // x hi
__device__ __align__(1024) __half g_as [(size_t)ROWS * K2];     // attn [hi | lo]
__device__ __align__(1024) __half g_wqkt[(size_t)QKV_C * CH];   // Wqkv^T hi
__device__ __align__(1024) __half g_wpt [(size_t)CH * K2];      // Wproj^T [hi | hi]

// ======================= helpers ===========================================
__device__ __forceinline__ uint32_t smem_u32(const void* p) {
    uint32_t a;
    asm("{ .reg .u64 t; cvta.to.shared.u64 t, %1; cvt.u32.u64 %0, t; }"
        : "=r"(a) : "l"(p));
    return a;
}

#define CP_ASYNC16(sm, gp) \
    asm volatile("cp.async.cg.shared.global [%0], [%1], 16;" :: "r"(sm), "l"(gp))
#define CP_COMMIT() asm volatile("cp.async.commit_group;" ::: "memory")
#define CP_WAIT1()  asm volatile("cp.async.wait_group 1;" ::: "memory")

__device__ __forceinline__ void ldsm_x4(uint32_t& r0, uint32_t& r1,
                                        uint32_t& r2, uint32_t& r3, uint32_t a) {
    asm volatile("ldmatrix.sync.aligned.m8n8.x4.shared.b16 {%0,%1,%2,%3}, [%4];"
                 : "=r"(r0), "=r"(r1), "=r"(r2), "=r"(r3) : "r"(a));
}
__device__ __forceinline__ void ldsm_x4t(uint32_t& r0, uint32_t& r1,
                                         uint32_t& r2, uint32_t& r3, uint32_t a) {
    asm volatile("ldmatrix.sync.aligned.m8n8.x4.trans.shared.b16 {%0,%1,%2,%3}, [%4];"
                 : "=r"(r0), "=r"(r1), "=r"(r2), "=r"(r3) : "r"(a));
}
__device__ __forceinline__ void mma16816(float* c, const uint32_t* a,
                                         const uint32_t* b) {
    asm volatile("mma.sync.aligned.m16n8k16.row.col.f32.f16.f16.f32 "
                 "{%0,%1,%2,%3}, {%4,%5,%6,%7}, {%8,%9}, {%0,%1,%2,%3};"
                 : "+f"(c[0]), "+f"(c[1]), "+f"(c[2]), "+f"(c[3])
                 : "r"(a[0]), "r"(a[1]), "r"(a[2]), "r"(a[3]),
                   "r"(b[0]), "r"(b[1]));
}
__device__ __forceinline__ uint32_t pack_h2(float a, float b) {
    __half2 h = __floats2half2_rn(a, b);
    return *(uint32_t*)&h;
}

// ---------------------------------------------------------------------------
// Conversions
// ---------------------------------------------------------------------------
__global__ void round_rows(const float* __restrict__ in, __half* __restrict__ out)
{
    size_t i = (size_t)blockIdx.x * blockDim.x + threadIdx.x;   // over ROWS*CH
    out[i] = __float2half(in[i]);
}

// W [CH, N] fp32 -> Wt [N, CH] fp16 hi (transpose + round)
__global__ void roundT(const float* __restrict__ W, __half* __restrict__ Wt, int N)
{
    __shared__ float t[32][33];
    int n0 = blockIdx.x * 32, k0 = blockIdx.y * 32;
    int tx = threadIdx.x, ty = threadIdx.y;   // 32 x 8
    #pragma unroll
    for (int j = 0; j < 32; j += 8)
        t[ty + j][tx] = W[(size_t)(k0 + ty + j) * N + n0 + tx];
    __syncthreads();
    #pragma unroll
    for (int j = 0; j < 32; j += 8)
        Wt[(size_t)(n0 + ty + j) * CH + k0 + tx] = __float2half(t[tx][ty + j]);
}

// W [CH, N] fp32 -> Wt [N, K2]: [0,CH)=hi, [CH,2CH)=hi (duplicated, proj)
__global__ void split_wT(const float* __restrict__ W, __half* __restrict__ Wt, int N)
{
    __shared__ float t[32][33];
    int n0 = blockIdx.x * 32, k0 = blockIdx.y * 32;
    int tx = threadIdx.x, ty = threadIdx.y;
    #pragma unroll
    for (int j = 0; j < 32; j += 8)
        t[ty + j][tx] = W[(size_t)(k0 + ty + j) * N + n0 + tx];
    __syncthreads();
    #pragma unroll
    for (int j = 0; j < 32; j += 8) {
        __half hi = __float2half(t[tx][ty + j]);
        __half* o = Wt + (size_t)(n0 + ty + j) * K2 + k0 + tx;
        o[0] = hi; o[CH] = hi;
    }
}

// ---------------------------------------------------------------------------
// mma.sync fp16 GEMM, fp32 acc. 128x128 CTA tile, BK=32, 8 warps (2x4),
// warp tile 64x32, 3-stage cp.async ring. Runtime strides + chunk count.
// MODE 0: fp32 out + bias.  MODE 1: fp16 out.
// ---------------------------------------------------------------------------
#define BK   32
#define LDSW 40
#define ASTG (128 * LDSW * 2)       // 10240 B per stage per operand
#define NSTG 3
#define GSM_BYTES (2 * NSTG * ASTG) // 61440

template<int MODE>
__global__ __launch_bounds__(256)
void gemm_mma(const __half* __restrict__ A, int lda,
              const __half* __restrict__ Bt, int ldb,
              const float* __restrict__ bias, float* __restrict__ C,
              __half* __restrict__ Ch, int N, int nchunk)
{
    extern __shared__ __align__(128) char gsm[];
    const uint32_t sb = smem_u32(gsm);

    const int tid  = threadIdx.x;
    const int lane = tid & 31;
    const int warp = tid >> 5;
    const int wm   = warp >> 2;      // 0..1
    const int wn   = warp & 3;       // 0..3
    const int m0   = blockIdx.y * 128;
    const int n0   = blockIdx.x * 128;

    const int crow = tid >> 2;
    const int ckp  = (tid & 3) * 8;
    const uint32_t so0 = (uint32_t)(crow * LDSW + ckp) * 2;
    const uint32_t so1 = (uint32_t)((crow + 64) * LDSW + ckp) * 2;

    auto load = [&](int kc, int buf) {
        const uint32_t sA = sb + buf * ASTG;
        const uint32_t sB = sb + NSTG * ASTG + buf * ASTG;
        const __half* Ag = A + (size_t)(m0 + crow) * lda + kc * BK + ckp;
        const __half* Bg = Bt + (size_t)(n0 + crow) * ldb + kc * BK + ckp;
        CP_ASYNC16(sA + so0, Ag);
        CP_ASYNC16(sA + so1, Ag + (size_t)64 * lda);
        CP_ASYNC16(sB + so0, Bg);
        CP_ASYNC16(sB + so1, Bg + (size_t)64 * ldb);
    };

    const int lmat = lane >> 3;
    const int lrow = lane & 7;
    const int a_row_base = wm * 64 + ((lmat & 1) << 3) + lrow;
    const int a_k_off    = (lmat >> 1) << 3;
    const int b_row_base = wn * 32 + ((lmat >> 1) << 3) + lrow;
    const int b_k_off    = (lmat & 1) << 3;

    float acc[4][4][4];
    #pragma unroll
    for (int i = 0; i < 4; i++)
        #pragma unroll
        for (int j = 0; j < 4; j++)
            #pragma unroll
            for (int q = 0; q < 4; q++) acc[i][j][q] = 0.0f;

    load(0, 0); CP_COMMIT();
    load(1, 1); CP_COMMIT();

    for (int t = 0; t < nchunk; t++) {
        const int buf = t % NSTG;
        CP_WAIT1();
        __syncthreads();
        if (t + 2 < nchunk) load(t + 2, (t + 2) % NSTG);
        CP_COMMIT();

        const uint32_t sA = sb + buf * ASTG;
        const uint32_t sB = sb + NSTG * ASTG + buf * ASTG;
        #pragma unroll
        for (int ks = 0; ks < 2; ks++) {
            uint32_t a[4][4];
            #pragma unroll
            for (int mt = 0; mt < 4; mt++)
                ldsm_x4(a[mt][0], a[mt][1], a[mt][2], a[mt][3],
                        sA + (uint32_t)((a_row_base + mt * 16) * LDSW
                                        + ks * 16 + a_k_off) * 2);
            uint32_t b[2][4];
            #pragma unroll
            for (int jj = 0; jj < 2; jj++)
                ldsm_x4(b[jj][0], b[jj][1], b[jj][2], b[jj][3],
                        sB + (uint32_t)((b_row_base + jj * 16) * LDSW
                                        + ks * 16 + b_k_off) * 2);
            #pragma unroll
            for (int mt = 0; mt < 4; mt++)
                #pragma unroll
                for (int nf = 0; nf < 4; nf++)
                    mma16816(acc[mt][nf], a[mt], &b[nf >> 1][(nf & 1) * 2]);
        }
    }

    const int emb = m0 + wm * 64 + (lane >> 2);
    const int enb = n0 + wn * 32 + (lane & 3) * 2;
    #pragma unroll
    for (int mt = 0; mt < 4; mt++) {
        #pragma unroll
        for (int nf = 0; nf < 4; nf++) {
            const int en = enb + nf * 8;
            const int em0 = emb + mt * 16;
            float v0 = acc[mt][nf][0], v1 = acc[mt][nf][1];
            float v2 = acc[mt][nf][2], v3 = acc[mt][nf][3];
            if (MODE == 0) {
                float b0 = bias[en], b1 = bias[en + 1];
                *(float2*)(C + (size_t)em0 * N + en)       = make_float2(v0 + b0, v1 + b1);
                *(float2*)(C + (size_t)(em0 + 8) * N + en) = make_float2(v2 + b0, v3 + b1);
            } else {
                *(uint32_t*)(Ch + (size_t)em0 * N + en)       = pack_h2(v0, v1);
                *(uint32_t*)(Ch + (size_t)(em0 + 8) * N + en) = pack_h2(v2, v3);
            }
        }
    }
}

// ---------------------------------------------------------------------------
// Tensorized causal flash attention (fp16 mma, fp32 acc, all-hi inputs).
// S = Q_hi K_hi^T (4 steps); O += P_hi V_hi (4 steps). 3-stage KV ring.
// Long (high-m) blocks scheduled first. Epilogue writes split proj input.
// ---------------------------------------------------------------------------
#define LDK 72
#define QS_HALVES (128 * LDK)              // 9216
#define KVSTG_HALVES (2 * 64 * LDK)        // 9216
#define AT_BYTES ((QS_HALVES + 3 * KVSTG_HALVES) * 2)   // 73728

__global__ __launch_bounds__(256, 2)
void flash_attn_mma(const __half* __restrict__ qh, __half* __restrict__ as)
{
    extern __shared__ __align__(128) __half hsm[];
    const uint32_t sQ = smem_u32(hsm);

    const int tid  = threadIdx.x;
    const int lane = tid & 31;
    const int warp = tid >> 5;
    const int bh = blockIdx.y;
    const int b  = bh >> 4;
    const int h  = bh & 15;
    const int m0 = ((int)gridDim.x - 1 - (int)blockIdx.x) * 128;  // long first

    const __half* Qh = qh + (size_t)b * SEQ * QKV_C + h * HDIM;
    const __half* Kh = Qh + CH;
    const __half* Vh = Qh + 2 * CH;

    auto kv_stage = [&](int s) -> uint32_t {
        return sQ + (uint32_t)(QS_HALVES + s * KVSTG_HALVES) * 2;
    };
    auto load_kv = [&](int t, int s) {
        const uint32_t sK = kv_stage(s);
        const uint32_t sV = sK + (uint32_t)(64 * LDK) * 2;
        #pragma unroll
        for (int i = 0; i < 2; i++) {
            int c = tid + i * 256;
            int r = c >> 3, j = (c & 7) * 8;
            size_t g = (size_t)(t * 64 + r) * QKV_C + j;
            CP_ASYNC16(sK + (uint32_t)(r * LDK + j) * 2, Kh + g);
            CP_ASYNC16(sV + (uint32_t)(r * LDK + j) * 2, Vh + g);
        }
    };

    // prologue: Q (hi only) + KV stages 0,1
    #pragma unroll
    for (int i = 0; i < 4; i++) {
        int c = tid + i * 256;                // 0..1023
        int r = c >> 3, j = (c & 7) * 8;
        CP_ASYNC16(sQ + (uint32_t)(r * LDK + j) * 2,
                   Qh + (size_t)(m0 + r) * QKV_C + j);
    }
    load_kv(0, 0); CP_COMMIT();
    load_kv(1, 1); CP_COMMIT();

    const int lmat = lane >> 3;
    const int lrow = lane & 7;
    const int a_row = warp * 16 + ((lmat & 1) << 3) + lrow;
    const int a_k   = (lmat >> 1) << 3;
    const int bs_rb = ((lmat >> 1) << 3) + lrow;
    const int bs_k  = (lmat & 1) << 3;
    const int bv_r  = ((lmat & 1) << 3) + lrow;
    const int bv_c  = (lmat >> 1) << 3;

    float m_i[2] = {-1e30f, -1e30f};
    float l_i[2] = {0.0f, 0.0f};
    float oacc[8][4];
    #pragma unroll
    for (int nf = 0; nf < 8; nf++)
        #pragma unroll
        for (int q = 0; q < 4; q++) oacc[nf][q] = 0.0f;

    const int r0 = m0 + warp * 16 + (lane >> 2);
    const int r1 = r0 + 8;

    const int ntiles = (m0 >> 6) + 2;
    for (int t = 0; t < ntiles; t++) {
        const int k0 = t << 6;
        CP_WAIT1();
        __syncthreads();
        if (t + 2 < ntiles) load_kv(t + 2, (t + 2) % 3);
        CP_COMMIT();

        const uint32_t sK = kv_stage(t % 3);
        const uint32_t sV = sK + (uint32_t)(64 * LDK) * 2;

        // ---- S = Q_hi K_hi^T : 4 k16 steps ----
        float sacc[8][4];
        #pragma unroll
        for (int nf = 0; nf < 8; nf++)
            #pragma unroll
            for (int q = 0; q < 4; q++) sacc[nf][q] = 0.0f;

        #pragma unroll
        for (int s = 0; s < 4; s++) {
            const int kb = s * 16;
            uint32_t a[4];
            ldsm_x4(a[0], a[1], a[2], a[3],
                    sQ + (uint32_t)(a_row * LDK + kb + a_k) * 2);
            #pragma unroll
            for (int nt = 0; nt < 4; nt++) {
                uint32_t bb[4];
                ldsm_x4(bb[0], bb[1], bb[2], bb[3],
                        sK + (uint32_t)((nt * 16 + bs_rb) * LDK + kb + bs_k) * 2);
                mma16816(sacc[nt * 2],     a, &bb[0]);
                mma16816(sacc[nt * 2 + 1], a, &bb[2]);
            }
        }

        // ---- online softmax ----
        const bool need_mask = (k0 + 63 > m0 + warp * 16);
        float mx0 = -1e30f, mx1 = -1e30f;
        #pragma unroll
        for (int nf = 0; nf < 8; nf++) {
            const int cb = k0 + nf * 8 + ((lane & 3) << 1);
            float v0 = sacc[nf][0] * 0.125f;
            float v1 = sacc[nf][1] * 0.125f;
            float v2 = sacc[nf][2] * 0.125f;
            float v3 = sacc[nf][3] * 0.125f;
            if (need_mask) {
                if (cb     > r0) v0 = -1e30f;
                if (cb + 1 > r0) v1 = -1e30f;
                if (cb     > r1) v2 = -1e30f;
                if (cb + 1 > r1) v3 = -1e30f;
            }
            sacc[nf][0] = v0; sacc[nf][1] = v1;
            sacc[nf][2] = v2; sacc[nf][3] = v3;
            mx0 = fmaxf(mx0, fmaxf(v0, v1));
            mx1 = fmaxf(mx1, fmaxf(v2, v3));
        }
        mx0 = fmaxf(mx0, __shfl_xor_sync(0xffffffffu, mx0, 1));
        mx0 = fmaxf(mx0, __shfl_xor_sync(0xffffffffu, mx0, 2));
        mx1 = fmaxf(mx1, __shfl_xor_sync(0xffffffffu, mx1, 1));
        mx1 = fmaxf(mx1, __shfl_xor_sync(0xffffffffu, mx1, 2));

        const float mn0 = fmaxf(m_i[0], mx0);
        const float mn1 = fmaxf(m_i[1], mx1);
        const float cr0 = __expf(m_i[0] - mn0);
        const float cr1 = __expf(m_i[1] - mn1);
        m_i[0] = mn0; m_i[1] = mn1;

        float sm0 = 0.f, sm1 = 0.f;
        #pragma unroll
        for (int nf = 0; nf < 8; nf++) {
            float p0 = __expf(sacc[nf][0] - mn0);
            float p1 = __expf(sacc[nf][1] - mn0);
            float p2 = __expf(sacc[nf][2] - mn1);
            float p3 = __expf(sacc[nf][3] - mn1);
            sacc[nf][0] = p0; sacc[nf][1] = p1;
            sacc[nf][2] = p2; sacc[nf][3] = p3;
            sm0 += p0 + p1;  sm1 += p2 + p3;
        }
        sm0 += __shfl_xor_sync(0xffffffffu, sm0, 1);
        sm0 += __shfl_xor_sync(0xffffffffu, sm0, 2);
        sm1 += __shfl_xor_sync(0xffffffffu, sm1, 1);
        sm1 += __shfl_xor_sync(0xffffffffu, sm1, 2);
        l_i[0] = l_i[0] * cr0 + sm0;
        l_i[1] = l_i[1] * cr1 + sm1;
        #pragma unroll
        for (int nf = 0; nf < 8; nf++) {
            oacc[nf][0] *= cr0; oacc[nf][1] *= cr0;
            oacc[nf][2] *= cr1; oacc[nf][3] *= cr1;
        }

        // ---- O += P_hi V_hi : 4 k16 steps ----
        #pragma unroll
        for (int s = 0; s < 4; s++) {
            const int kb = s * 16;
            uint32_t pa[4];
            pa[0] = pack_h2(sacc[2 * s][0],     sacc[2 * s][1]);
            pa[1] = pack_h2(sacc[2 * s][2],     sacc[2 * s][3]);
            pa[2] = pack_h2(sacc[2 * s + 1][0], sacc[2 * s + 1][1]);
            pa[3] = pack_h2(sacc[2 * s + 1][2], sacc[2 * s + 1][3]);
            #pragma unroll
            for (int nt = 0; nt < 4; nt++) {
                uint32_t bb[4];
                ldsm_x4t(bb[0], bb[1], bb[2], bb[3],
                         sV + (uint32_t)((kb + bv_r) * LDK + nt * 16 + bv_c) * 2);
                mma16816(oacc[nt * 2],     pa, &bb[0]);
                mma16816(oacc[nt * 2 + 1], pa, &bb[2]);
            }
        }
    }

    // ---- epilogue: normalize + fused split write to g_as [hi | lo] ----
    const float inv0 = 1.0f / l_i[0];
    const float inv1 = 1.0f / l_i[1];
    const size_t row0 = (size_t)(b * SEQ + r0) * K2;
    const size_t row1 = (size_t)(b * SEQ + r1) * K2;
    #pragma unroll
    for (int nf = 0; nf < 8; nf++) {
        const int col = h * HDIM + nf * 8 + ((lane & 3) << 1);
        float v0 = oacc[nf][0] * inv0, v1 = oacc[nf][1] * inv0;
        float v2 = oacc[nf][2] * inv1, v3 = oacc[nf][3] * inv1;

        uint32_t hiA = pack_h2(v0, v1);
        __half2 hA = *(__half2*)&hiA;
        uint32_t loA = pack_h2(v0 - __low2float(hA), v1 - __high2float(hA));
        uint32_t hiB = pack_h2(v2, v3);
        __half2 hB = *(__half2*)&hiB;
        uint32_t loB = pack_h2(v2 - __low2float(hB), v3 - __high2float(hB));

        *(uint32_t*)(as + row0 + col)      = hiA;
        *(uint32_t*)(as + row0 + CH + col) = loA;
        *(uint32_t*)(as + row1 + col)      = hiB;
        *(uint32_t*)(as + row1 + CH + col) = loB;
    }
}

// ---------------------------------------------------------------------------
extern "C" void kernel_launch(void* const* d_in, const int* in_sizes, int n_in,
                              void* d_out, int out_size)
{
    const float* x     = (const float*)d_in[0];
    const float* Wqkv  = (const float*)d_in[2];
    const float* Wproj = (const float*)d_in[3];
    const float* bproj = (const float*)d_in[4];
    float* out = (float*)d_out;

    void *p_qh, *p_xh, *p_as, *p_wqkt, *p_wpt;
    cudaGetSymbolAddress(&p_qh, g_qh);
    cudaGetSymbolAddress(&p_xh, g_xh);
    cudaGetSymbolAddress(&p_as, g_as);
    cudaGetSymbolAddress(&p_wqkt, g_wqkt);
    cudaGetSymbolAddress(&p_wpt, g_wpt);
    __half* qh   = (__half*)p_qh;
    __half* xh   = (__half*)p_xh;
    __half* as   = (__half*)p_as;
    __half* wqkt = (__half*)p_wqkt;
    __half* wpt  = (__half*)p_wpt;

    cudaFuncSetAttribute(gemm_mma<0>, cudaFuncAttributeMaxDynamicSharedMemorySize,
                         GSM_BYTES);
    cudaFuncSetAttribute(gemm_mma<1>, cudaFuncAttributeMaxDynamicSharedMemorySize,
                         GSM_BYTES);
    cudaFuncSetAttribute(flash_attn_mma, cudaFuncAttributeMaxDynamicSharedMemorySize,
                         AT_BYTES);

    // conversions
    round_rows<<<(ROWS * CH) / 256, 256>>>(x, xh);
    dim3 wt1(QKV_C / 32, CH / 32);
    roundT<<<wt1, dim3(32, 8)>>>(Wqkv, wqkt, QKV_C);
    dim3 wt2(CH / 32, CH / 32);
    split_wT<<<wt2, dim3(32, 8)>>>(Wproj, wpt, CH);

    // 1) qkv = x_hi @ Wqkv_hi  (single hi-only GEMM, K=1024)
    dim3 g1(QKV_C / 128, ROWS / 128);
    gemm_mma<1><<<g1, 256, GSM_BYTES>>>(xh, CH, wqkt, CH, nullptr, nullptr,
                                        qh, QKV_C, CH / BK);

    // 2) causal flash attention -> split proj input (fused)
    dim3 g2(SEQ / 128, BATCH * HEADS);
    flash_attn_mma<<<g2, 256, AT_BYTES>>>(qh, as);

    // 3) out = (a_hi + a_lo) @ Wproj_hi + b   (split K=2048)
    dim3 g3(CH / 128, ROWS / 128);
    gemm_mma<0><<<g3, 256, GSM_BYTES>>>(as, K2, wpt, K2, bproj, out,
                                        nullptr, CH, K2 / BK);
}